// round 5
// baseline (speedup 1.0000x reference)
#include <cuda_runtime.h>
#include <math.h>

#define BB 2
#define HH 720
#define WW 1280
#define HW (HH*WW)
#define NPIX (BB*HW)
#define EPSF 1e-7f

// Scratch: splat accumulators [dir][b][pixel][4ch]  (~59 MB)
__device__ __align__(16) float g_acc[(size_t)2 * BB * HW * 4];

// ---------------------------------------------------------------------------
// Splat kernel: each thread handles FOUR consecutive source pixels (x-aligned),
// both warp directions. All input loads are LDG.128; scatter via RED.E.128.
// ---------------------------------------------------------------------------
#define QPIX (NPIX / 4)
#define QHW  (HW / 4)

__global__ void __launch_bounds__(256) splat_kernel(
    const float* __restrict__ img0, const float* __restrict__ img1,
    const float* __restrict__ flow0, const float* __restrict__ flow1,
    const float* __restrict__ z0, const float* __restrict__ z1)
{
    int i4 = blockIdx.x * blockDim.x + threadIdx.x;
    if (i4 >= QPIX) return;
    int b = i4 / QHW;
    int p4 = i4 - b * QHW;
    int p = p4 * 4;
    int y = p / WW;
    int x = p - y * WW;

#pragma unroll
    for (int d = 0; d < 2; ++d) {
        const float* img = d ? img1 : img0;
        const float* fl  = d ? flow0 : flow1;
        const float* zz  = d ? z0 : z1;

        // Vector loads: 4 pixels at once
        float4 flx = *reinterpret_cast<const float4*>(fl + (size_t)(b * 2 + 1) * HW + p);
        float4 fly = *reinterpret_cast<const float4*>(fl + (size_t)(b * 2 + 0) * HW + p);
        float4 zv  = *reinterpret_cast<const float4*>(zz + (size_t)b * HW + p);
        float4 rv  = *reinterpret_cast<const float4*>(img + (size_t)(b * 3 + 0) * HW + p);
        float4 gv  = *reinterpret_cast<const float4*>(img + (size_t)(b * 3 + 1) * HW + p);
        float4 bv  = *reinterpret_cast<const float4*>(img + (size_t)(b * 3 + 2) * HW + p);

        float4* acc = reinterpret_cast<float4*>(g_acc) + (size_t)(d * BB + b) * HW;

        const float* flxp = (const float*)&flx;
        const float* flyp = (const float*)&fly;
        const float* zp   = (const float*)&zv;
        const float* rp   = (const float*)&rv;
        const float* gp   = (const float*)&gv;
        const float* bp   = (const float*)&bv;

#pragma unroll
        for (int j = 0; j < 4; ++j) {
            float fx = (float)(x + j) + 0.5f * flxp[j];
            float fy = (float)y + 0.5f * flyp[j];
            float w  = __expf(zp[j]);
            float vr = rp[j] * w;
            float vg = gp[j] * w;
            float vb = bp[j] * w;

            float x0f = floorf(fx), y0f = floorf(fy);
            int ix0 = (int)x0f, iy0 = (int)y0f;
            float ax = fx - x0f, ay = fy - y0f;

#pragma unroll
            for (int cy = 0; cy < 2; ++cy) {
                int ty = iy0 + cy;
                if ((unsigned)ty >= (unsigned)HH) continue;
                float wy = cy ? ay : (1.0f - ay);
#pragma unroll
                for (int cx = 0; cx < 2; ++cx) {
                    int tx = ix0 + cx;
                    if ((unsigned)tx >= (unsigned)WW) continue;
                    float wt = wy * (cx ? ax : (1.0f - ax));
                    atomicAdd(acc + ((size_t)ty * WW + tx),
                              make_float4(vr * wt, vg * wt, vb * wt, w * wt));
                }
            }
        }
    }
}

// ---------------------------------------------------------------------------
// Fused normalize + morphological open + compose (R3 variant: 32x16 tile,
// 512 threads, 1 px/thread — best measured occupancy/latency tradeoff).
// Template-specialized on radius R.
// ---------------------------------------------------------------------------
#define TTX 32
#define TTY 16
#define RMAX 4
#define INW_MAX (TTX + 4 * RMAX)   // 48
#define INH_MAX (TTY + 4 * RMAX)   // 32
#define HMW_MAX (TTX + 2 * RMAX)   // 40
#define EH_MAX  (TTY + 2 * RMAX)   // 24
#define NT (TTX * TTY)

struct SmemT {
    float s_in[2][INH_MAX][INW_MAX];
    float s_hm[2][INH_MAX][HMW_MAX];
    float s_er[2][EH_MAX][HMW_MAX];
    float s_hx[2][EH_MAX][TTX];
};

template<int R>
__device__ __forceinline__ void open_body(
    SmemT& S,
    const float* __restrict__ flow0, const float* __restrict__ flow1,
    float* __restrict__ out)
{
    constexpr int INW = TTX + 4 * R;
    constexpr int INH = TTY + 4 * R;
    constexpr int HMW = TTX + 2 * R;
    constexpr int EH  = TTY + 2 * R;
    constexpr int WIN = 2 * R;

    const float PINF = __int_as_float(0x7f800000);
    const float NINF = __int_as_float(0xff800000);

    int b  = blockIdx.z;
    int ox = blockIdx.x * TTX;
    int oy = blockIdx.y * TTY;
    int tid = threadIdx.y * TTX + threadIdx.x;

    int txx = threadIdx.x, tyy = threadIdx.y;
    int gx = ox + txx, gy = oy + tyy;
    bool inimg = (gx < WW) && (gy < HH);
    size_t p = (size_t)gy * WW + gx;
    float4 a0 = make_float4(0.f, 0.f, 0.f, 0.f);
    float4 a1 = a0;
    if (inimg) {
        a0 = reinterpret_cast<const float4*>(g_acc)[(size_t)(0 * BB + b) * HW + p];
        a1 = reinterpret_cast<const float4*>(g_acc)[(size_t)(1 * BB + b) * HW + p];
    }
    float i0 = 1.0f / (a0.w + EPSF);
    float i1 = 1.0f / (a1.w + EPSF);
    float f01r = a0.x * i0, f01g = a0.y * i0, f01b = a0.z * i0;
    float f10r = a1.x * i1, f10g = a1.y * i1, f10b = a1.z * i1;

#pragma unroll
    for (int m = 0; m < 2; ++m) {
        const float* wbase = g_acc + ((size_t)(m * BB + b) * HW << 2) + 3;
#pragma unroll 2
        for (int idx = tid; idx < INH * INW; idx += NT) {
            int iy = idx / INW;
            int ix = idx - iy * INW;
            int hy = oy - 2 * R + iy;
            int hx = ox - 2 * R + ix;
            float v = PINF;
            if ((unsigned)hy < (unsigned)HH && (unsigned)hx < (unsigned)WW) {
                float wv = wbase[((size_t)hy * WW + hx) << 2];
                v = wv / (wv + EPSF);
            }
            S.s_in[m][iy][ix] = v;
        }
    }
    __syncthreads();

#pragma unroll
    for (int m = 0; m < 2; ++m) {
#pragma unroll 2
        for (int idx = tid; idx < INH * HMW; idx += NT) {
            int iy = idx / HMW;
            int hx = idx - iy * HMW;
            float v = S.s_in[m][iy][hx];
#pragma unroll
            for (int dd = 1; dd <= WIN; ++dd) v = fminf(v, S.s_in[m][iy][hx + dd]);
            S.s_hm[m][iy][hx] = v;
        }
    }
    __syncthreads();

#pragma unroll
    for (int m = 0; m < 2; ++m) {
#pragma unroll 2
        for (int idx = tid; idx < EH * HMW; idx += NT) {
            int ey = idx / HMW;
            int hx = idx - ey * HMW;
            int hy = oy - R + ey;
            int hgx = ox - R + hx;
            float v = NINF;
            if ((unsigned)hy < (unsigned)HH && (unsigned)hgx < (unsigned)WW) {
                v = S.s_hm[m][ey][hx];
#pragma unroll
                for (int dd = 1; dd <= WIN; ++dd) v = fminf(v, S.s_hm[m][ey + dd][hx]);
            }
            S.s_er[m][ey][hx] = v;
        }
    }
    __syncthreads();

#pragma unroll
    for (int m = 0; m < 2; ++m) {
#pragma unroll 2
        for (int idx = tid; idx < EH * TTX; idx += NT) {
            int ey = idx / TTX;
            int xx = idx - ey * TTX;
            float v = S.s_er[m][ey][xx];
#pragma unroll
            for (int dd = 1; dd <= WIN; ++dd) v = fmaxf(v, S.s_er[m][ey][xx + dd]);
            S.s_hx[m][ey][xx] = v;
        }
    }
    __syncthreads();

    if (inimg) {
        float m01 = S.s_hx[0][tyy][txx];
        float m10 = S.s_hx[1][tyy][txx];
#pragma unroll
        for (int dd = 1; dd <= WIN; ++dd) {
            m01 = fmaxf(m01, S.s_hx[0][tyy + dd][txx]);
            m10 = fmaxf(m10, S.s_hx[1][tyy + dd][txx]);
        }
        float* ob = out + (size_t)b * 18 * HW;
        ob[(size_t)0  * HW + p] = m01 * f01r + (1.0f - m01) * f10r;
        ob[(size_t)1  * HW + p] = m01 * f01g + (1.0f - m01) * f10g;
        ob[(size_t)2  * HW + p] = m01 * f01b + (1.0f - m01) * f10b;
        ob[(size_t)3  * HW + p] = m10 * f10r + (1.0f - m10) * f01r;
        ob[(size_t)4  * HW + p] = m10 * f10g + (1.0f - m10) * f01g;
        ob[(size_t)5  * HW + p] = m10 * f10b + (1.0f - m10) * f01b;
        ob[(size_t)6  * HW + p] = f01r;
        ob[(size_t)7  * HW + p] = f01g;
        ob[(size_t)8  * HW + p] = f01b;
        ob[(size_t)9  * HW + p] = f10r;
        ob[(size_t)10 * HW + p] = f10g;
        ob[(size_t)11 * HW + p] = f10b;
        ob[(size_t)12 * HW + p] = 0.5f * flow0[(size_t)(b * 2 + 0) * HW + p];
        ob[(size_t)13 * HW + p] = 0.5f * flow0[(size_t)(b * 2 + 1) * HW + p];
        ob[(size_t)14 * HW + p] = 0.5f * flow1[(size_t)(b * 2 + 0) * HW + p];
        ob[(size_t)15 * HW + p] = 0.5f * flow1[(size_t)(b * 2 + 1) * HW + p];
        ob[(size_t)16 * HW + p] = m01;
        ob[(size_t)17 * HW + p] = m10;
    }
}

__global__ void __launch_bounds__(NT) open_compose_kernel(
    const int* __restrict__ kptr,
    const float* __restrict__ flow0, const float* __restrict__ flow1,
    float* __restrict__ out)
{
    __shared__ SmemT S;

    int kk = kptr[0];
    int r = (kk >= 2) ? (kk - 1) / 2 : 0;
    if (r > RMAX) r = RMAX;

    switch (r) {
        case 0: open_body<0>(S, flow0, flow1, out); break;
        case 1: open_body<1>(S, flow0, flow1, out); break;
        case 2: open_body<2>(S, flow0, flow1, out); break;
        case 3: open_body<3>(S, flow0, flow1, out); break;
        default: open_body<4>(S, flow0, flow1, out); break;
    }
}

// ---------------------------------------------------------------------------
extern "C" void kernel_launch(void* const* d_in, const int* in_sizes, int n_in,
                              void* d_out, int out_size)
{
    const float* img0  = (const float*)d_in[0];
    const float* img1  = (const float*)d_in[1];
    const float* flow0 = (const float*)d_in[2];
    const float* flow1 = (const float*)d_in[3];
    const float* z0    = (const float*)d_in[4];
    const float* z1    = (const float*)d_in[5];
    const int*   kptr  = (const int*)d_in[6];
    float* out = (float*)d_out;

    // Clear accumulators (memset node in the captured graph)
    void* accPtr = nullptr;
    cudaGetSymbolAddress(&accPtr, g_acc);
    cudaMemsetAsync(accPtr, 0, sizeof(float) * (size_t)2 * BB * HW * 4, 0);

    int threads = 256;
    int blocks = (QPIX + threads - 1) / threads;
    splat_kernel<<<blocks, threads>>>(img0, img1, flow0, flow1, z0, z1);

    dim3 gblk(TTX, TTY, 1);
    dim3 ggrid((WW + TTX - 1) / TTX, (HH + TTY - 1) / TTY, BB);
    open_compose_kernel<<<ggrid, gblk>>>(kptr, flow0, flow1, out);
}

// round 6
// speedup vs baseline: 1.2067x; 1.2067x over previous
#include <cuda_runtime.h>
#include <math.h>

#define BB 2
#define HH 720
#define WW 1280
#define HW (HH*WW)
#define NPIX (BB*HW)
#define EPSF 1e-7f

// Scratch: splat accumulators [dir][b][pixel][4ch]  (~59 MB)
__device__ __align__(16) float g_acc[(size_t)2 * BB * HW * 4];

// ---------------------------------------------------------------------------
// Splat kernel (scalar, 1 px/thread — measured REDG floor ~62us; best known).
// sm_90+ float4 atomicAdd -> one RED.E.128 per corner.
// ---------------------------------------------------------------------------
__global__ void __launch_bounds__(256) splat_kernel(
    const float* __restrict__ img0, const float* __restrict__ img1,
    const float* __restrict__ flow0, const float* __restrict__ flow1,
    const float* __restrict__ z0, const float* __restrict__ z1)
{
    int i = blockIdx.x * blockDim.x + threadIdx.x;
    if (i >= NPIX) return;
    int b = i / HW;
    int p = i - b * HW;
    int y = p / WW;
    int x = p - y * WW;

#pragma unroll
    for (int d = 0; d < 2; ++d) {
        const float* img = d ? img1 : img0;
        const float* fl  = d ? flow0 : flow1;
        const float* zz  = d ? z0 : z1;

        float fx = (float)x + 0.5f * fl[(size_t)(b * 2 + 1) * HW + p];
        float fy = (float)y + 0.5f * fl[(size_t)(b * 2 + 0) * HW + p];
        float w  = __expf(zz[(size_t)b * HW + p]);
        float vr = img[(size_t)(b * 3 + 0) * HW + p] * w;
        float vg = img[(size_t)(b * 3 + 1) * HW + p] * w;
        float vb = img[(size_t)(b * 3 + 2) * HW + p] * w;

        float x0f = floorf(fx), y0f = floorf(fy);
        int ix0 = (int)x0f, iy0 = (int)y0f;
        float ax = fx - x0f, ay = fy - y0f;

        float4* acc = reinterpret_cast<float4*>(g_acc) + (size_t)(d * BB + b) * HW;
#pragma unroll
        for (int cy = 0; cy < 2; ++cy) {
            int ty = iy0 + cy;
            if ((unsigned)ty >= (unsigned)HH) continue;
            float wy = cy ? ay : (1.0f - ay);
#pragma unroll
            for (int cx = 0; cx < 2; ++cx) {
                int tx = ix0 + cx;
                if ((unsigned)tx >= (unsigned)WW) continue;
                float wt = wy * (cx ? ax : (1.0f - ax));
                atomicAdd(acc + ((size_t)ty * WW + tx),
                          make_float4(vr * wt, vg * wt, vb * wt, w * wt));
            }
        }
    }
}

// ---------------------------------------------------------------------------
// Fused normalize + morphological open + compose.
// Monotone trick: open() is applied to RAW w (not w/(w+eps)); the strictly
// increasing map f(w)=w/(w+eps) commutes with min/max, applied only at the end.
// Both masks (m=0,1) processed interleaved in each stage loop for ILP.
// Tile 32x16, 512 threads, template-specialized on radius R.
// ---------------------------------------------------------------------------
#define TTX 32
#define TTY 16
#define RMAX 4
#define INW_MAX (TTX + 4 * RMAX)   // 48
#define INH_MAX (TTY + 4 * RMAX)   // 32
#define HMW_MAX (TTX + 2 * RMAX)   // 40
#define EH_MAX  (TTY + 2 * RMAX)   // 24
#define NT (TTX * TTY)

struct SmemT {
    float s_in[2][INH_MAX][INW_MAX];
    float s_hm[2][INH_MAX][HMW_MAX];
    float s_er[2][EH_MAX][HMW_MAX];
    float s_hx[2][EH_MAX][TTX];
};

template<int R>
__device__ __forceinline__ void open_body(
    SmemT& S,
    const float* __restrict__ flow0, const float* __restrict__ flow1,
    float* __restrict__ out)
{
    constexpr int INW = TTX + 4 * R;
    constexpr int INH = TTY + 4 * R;
    constexpr int HMW = TTX + 2 * R;
    constexpr int EH  = TTY + 2 * R;
    constexpr int WIN = 2 * R;

    const float PINF = __int_as_float(0x7f800000);
    const float NINF = __int_as_float(0xff800000);

    int b  = blockIdx.z;
    int ox = blockIdx.x * TTX;
    int oy = blockIdx.y * TTY;
    int tid = threadIdx.y * TTX + threadIdx.x;

    int txx = threadIdx.x, tyy = threadIdx.y;
    int gx = ox + txx, gy = oy + tyy;
    bool inimg = (gx < WW) && (gy < HH);
    size_t p = (size_t)gy * WW + gx;
    float4 a0 = make_float4(0.f, 0.f, 0.f, 0.f);
    float4 a1 = a0;
    if (inimg) {
        a0 = reinterpret_cast<const float4*>(g_acc)[(size_t)(0 * BB + b) * HW + p];
        a1 = reinterpret_cast<const float4*>(g_acc)[(size_t)(1 * BB + b) * HW + p];
    }
    float i0 = 1.0f / (a0.w + EPSF);
    float i1 = 1.0f / (a1.w + EPSF);
    float f01r = a0.x * i0, f01g = a0.y * i0, f01b = a0.z * i0;
    float f10r = a1.x * i1, f10g = a1.y * i1, f10b = a1.z * i1;

    // Stage 1: load RAW w into halo; +inf outside image (erosion pad).
    {
        const float* w0 = g_acc + ((size_t)(0 * BB + b) * HW << 2) + 3;
        const float* w1 = g_acc + ((size_t)(1 * BB + b) * HW << 2) + 3;
#pragma unroll 2
        for (int idx = tid; idx < INH * INW; idx += NT) {
            int iy = idx / INW;
            int ix = idx - iy * INW;
            int hy = oy - 2 * R + iy;
            int hx = ox - 2 * R + ix;
            float v0 = PINF, v1 = PINF;
            if ((unsigned)hy < (unsigned)HH && (unsigned)hx < (unsigned)WW) {
                size_t o = ((size_t)hy * WW + hx) << 2;
                v0 = w0[o];
                v1 = w1[o];
            }
            S.s_in[0][iy][ix] = v0;
            S.s_in[1][iy][ix] = v1;
        }
    }
    __syncthreads();

    // Stage 2: horizontal min (both masks per iteration)
#pragma unroll 2
    for (int idx = tid; idx < INH * HMW; idx += NT) {
        int iy = idx / HMW;
        int hx = idx - iy * HMW;
        float v0 = S.s_in[0][iy][hx];
        float v1 = S.s_in[1][iy][hx];
#pragma unroll
        for (int dd = 1; dd <= WIN; ++dd) {
            v0 = fminf(v0, S.s_in[0][iy][hx + dd]);
            v1 = fminf(v1, S.s_in[1][iy][hx + dd]);
        }
        S.s_hm[0][iy][hx] = v0;
        S.s_hm[1][iy][hx] = v1;
    }
    __syncthreads();

    // Stage 3: vertical min -> erosion; out-of-image -> -inf (dilation pad)
#pragma unroll 2
    for (int idx = tid; idx < EH * HMW; idx += NT) {
        int ey = idx / HMW;
        int hx = idx - ey * HMW;
        int hy = oy - R + ey;
        int hgx = ox - R + hx;
        float v0 = NINF, v1 = NINF;
        if ((unsigned)hy < (unsigned)HH && (unsigned)hgx < (unsigned)WW) {
            v0 = S.s_hm[0][ey][hx];
            v1 = S.s_hm[1][ey][hx];
#pragma unroll
            for (int dd = 1; dd <= WIN; ++dd) {
                v0 = fminf(v0, S.s_hm[0][ey + dd][hx]);
                v1 = fminf(v1, S.s_hm[1][ey + dd][hx]);
            }
        }
        S.s_er[0][ey][hx] = v0;
        S.s_er[1][ey][hx] = v1;
    }
    __syncthreads();

    // Stage 4: horizontal max
#pragma unroll 2
    for (int idx = tid; idx < EH * TTX; idx += NT) {
        int ey = idx / TTX;
        int xx = idx - ey * TTX;
        float v0 = S.s_er[0][ey][xx];
        float v1 = S.s_er[1][ey][xx];
#pragma unroll
        for (int dd = 1; dd <= WIN; ++dd) {
            v0 = fmaxf(v0, S.s_er[0][ey][xx + dd]);
            v1 = fmaxf(v1, S.s_er[1][ey][xx + dd]);
        }
        S.s_hx[0][ey][xx] = v0;
        S.s_hx[1][ey][xx] = v1;
    }
    __syncthreads();

    // Stage 5: vertical max -> opened raw w; apply f(w)=w/(w+eps); compose.
    if (inimg) {
        float w01 = S.s_hx[0][tyy][txx];
        float w10 = S.s_hx[1][tyy][txx];
#pragma unroll
        for (int dd = 1; dd <= WIN; ++dd) {
            w01 = fmaxf(w01, S.s_hx[0][tyy + dd][txx]);
            w10 = fmaxf(w10, S.s_hx[1][tyy + dd][txx]);
        }
        float m01 = w01 / (w01 + EPSF);
        float m10 = w10 / (w10 + EPSF);

        float* ob = out + (size_t)b * 18 * HW;
        ob[(size_t)0  * HW + p] = m01 * f01r + (1.0f - m01) * f10r;
        ob[(size_t)1  * HW + p] = m01 * f01g + (1.0f - m01) * f10g;
        ob[(size_t)2  * HW + p] = m01 * f01b + (1.0f - m01) * f10b;
        ob[(size_t)3  * HW + p] = m10 * f10r + (1.0f - m10) * f01r;
        ob[(size_t)4  * HW + p] = m10 * f10g + (1.0f - m10) * f01g;
        ob[(size_t)5  * HW + p] = m10 * f10b + (1.0f - m10) * f01b;
        ob[(size_t)6  * HW + p] = f01r;
        ob[(size_t)7  * HW + p] = f01g;
        ob[(size_t)8  * HW + p] = f01b;
        ob[(size_t)9  * HW + p] = f10r;
        ob[(size_t)10 * HW + p] = f10g;
        ob[(size_t)11 * HW + p] = f10b;
        ob[(size_t)12 * HW + p] = 0.5f * flow0[(size_t)(b * 2 + 0) * HW + p];
        ob[(size_t)13 * HW + p] = 0.5f * flow0[(size_t)(b * 2 + 1) * HW + p];
        ob[(size_t)14 * HW + p] = 0.5f * flow1[(size_t)(b * 2 + 0) * HW + p];
        ob[(size_t)15 * HW + p] = 0.5f * flow1[(size_t)(b * 2 + 1) * HW + p];
        ob[(size_t)16 * HW + p] = m01;
        ob[(size_t)17 * HW + p] = m10;
    }
}

__global__ void __launch_bounds__(NT) open_compose_kernel(
    const int* __restrict__ kptr,
    const float* __restrict__ flow0, const float* __restrict__ flow1,
    float* __restrict__ out)
{
    __shared__ SmemT S;

    int kk = kptr[0];
    int r = (kk >= 2) ? (kk - 1) / 2 : 0;
    if (r > RMAX) r = RMAX;

    switch (r) {
        case 0: open_body<0>(S, flow0, flow1, out); break;
        case 1: open_body<1>(S, flow0, flow1, out); break;
        case 2: open_body<2>(S, flow0, flow1, out); break;
        case 3: open_body<3>(S, flow0, flow1, out); break;
        default: open_body<4>(S, flow0, flow1, out); break;
    }
}

// ---------------------------------------------------------------------------
extern "C" void kernel_launch(void* const* d_in, const int* in_sizes, int n_in,
                              void* d_out, int out_size)
{
    const float* img0  = (const float*)d_in[0];
    const float* img1  = (const float*)d_in[1];
    const float* flow0 = (const float*)d_in[2];
    const float* flow1 = (const float*)d_in[3];
    const float* z0    = (const float*)d_in[4];
    const float* z1    = (const float*)d_in[5];
    const int*   kptr  = (const int*)d_in[6];
    float* out = (float*)d_out;

    // Clear accumulators (memset node in the captured graph)
    void* accPtr = nullptr;
    cudaGetSymbolAddress(&accPtr, g_acc);
    cudaMemsetAsync(accPtr, 0, sizeof(float) * (size_t)2 * BB * HW * 4, 0);

    int threads = 256;
    int blocks = (NPIX + threads - 1) / threads;
    splat_kernel<<<blocks, threads>>>(img0, img1, flow0, flow1, z0, z1);

    dim3 gblk(TTX, TTY, 1);
    dim3 ggrid((WW + TTX - 1) / TTX, (HH + TTY - 1) / TTY, BB);
    open_compose_kernel<<<ggrid, gblk>>>(kptr, flow0, flow1, out);
}

// round 7
// speedup vs baseline: 1.2232x; 1.0137x over previous
#include <cuda_runtime.h>
#include <math.h>

#define BB 2
#define HH 720
#define WW 1280
#define HW (HH*WW)
#define NPIX (BB*HW)
#define EPSF 1e-7f

// Scratch: splat accumulators [dir][b][pixel][4ch]  (~59 MB)
__device__ __align__(16) float g_acc[(size_t)2 * BB * HW * 4];

// ---------------------------------------------------------------------------
// Splat kernel (scalar, 1 px/thread — measured REDG-lane floor ~62us).
// sm_90+ float4 atomicAdd -> one RED.E.128 per corner.
// ---------------------------------------------------------------------------
__global__ void __launch_bounds__(256) splat_kernel(
    const float* __restrict__ img0, const float* __restrict__ img1,
    const float* __restrict__ flow0, const float* __restrict__ flow1,
    const float* __restrict__ z0, const float* __restrict__ z1)
{
    int i = blockIdx.x * blockDim.x + threadIdx.x;
    if (i >= NPIX) return;
    int b = i / HW;
    int p = i - b * HW;
    int y = p / WW;
    int x = p - y * WW;

#pragma unroll
    for (int d = 0; d < 2; ++d) {
        const float* img = d ? img1 : img0;
        const float* fl  = d ? flow0 : flow1;
        const float* zz  = d ? z0 : z1;

        float fx = (float)x + 0.5f * fl[(size_t)(b * 2 + 1) * HW + p];
        float fy = (float)y + 0.5f * fl[(size_t)(b * 2 + 0) * HW + p];
        float w  = __expf(zz[(size_t)b * HW + p]);
        float vr = img[(size_t)(b * 3 + 0) * HW + p] * w;
        float vg = img[(size_t)(b * 3 + 1) * HW + p] * w;
        float vb = img[(size_t)(b * 3 + 2) * HW + p] * w;

        float x0f = floorf(fx), y0f = floorf(fy);
        int ix0 = (int)x0f, iy0 = (int)y0f;
        float ax = fx - x0f, ay = fy - y0f;

        float4* acc = reinterpret_cast<float4*>(g_acc) + (size_t)(d * BB + b) * HW;
#pragma unroll
        for (int cy = 0; cy < 2; ++cy) {
            int ty = iy0 + cy;
            if ((unsigned)ty >= (unsigned)HH) continue;
            float wy = cy ? ay : (1.0f - ay);
#pragma unroll
            for (int cx = 0; cx < 2; ++cx) {
                int tx = ix0 + cx;
                if ((unsigned)tx >= (unsigned)WW) continue;
                float wt = wy * (cx ? ax : (1.0f - ax));
                atomicAdd(acc + ((size_t)ty * WW + tx),
                          make_float4(vr * wt, vg * wt, vb * wt, w * wt));
            }
        }
    }
}

// ---------------------------------------------------------------------------
// Fused normalize + morphological open + compose.
// - open() on RAW w (monotone map applied only at the end)
// - both masks interleaved for ILP
// - stages 2-4 produce 2 adjacent outputs per iteration (sliding window:
//   WIN+2 taps shared between the pair instead of 2*(WIN+1))
// - final stores use streaming hint (__stcs)
// Tile 32x16, 512 threads, template-specialized on radius R.
// ---------------------------------------------------------------------------
#define TTX 32
#define TTY 16
#define RMAX 4
#define INW_MAX (TTX + 4 * RMAX)   // 48
#define INH_MAX (TTY + 4 * RMAX)   // 32
#define HMW_MAX (TTX + 2 * RMAX)   // 40
#define EH_MAX  (TTY + 2 * RMAX)   // 24
#define NT (TTX * TTY)

struct SmemT {
    float s_in[2][INH_MAX][INW_MAX];
    float s_hm[2][INH_MAX][HMW_MAX];
    float s_er[2][EH_MAX][HMW_MAX];
    float s_hx[2][EH_MAX][TTX];
};

template<int R>
__device__ __forceinline__ void open_body(
    SmemT& S,
    const float* __restrict__ flow0, const float* __restrict__ flow1,
    float* __restrict__ out)
{
    constexpr int INW = TTX + 4 * R;
    constexpr int INH = TTY + 4 * R;
    constexpr int HMW = TTX + 2 * R;   // even
    constexpr int EH  = TTY + 2 * R;   // even
    constexpr int WIN = 2 * R;

    const float PINF = __int_as_float(0x7f800000);
    const float NINF = __int_as_float(0xff800000);

    int b  = blockIdx.z;
    int ox = blockIdx.x * TTX;
    int oy = blockIdx.y * TTY;
    int tid = threadIdx.y * TTX + threadIdx.x;

    int txx = threadIdx.x, tyy = threadIdx.y;
    int gx = ox + txx, gy = oy + tyy;
    bool inimg = (gx < WW) && (gy < HH);
    size_t p = (size_t)gy * WW + gx;
    float4 a0 = make_float4(0.f, 0.f, 0.f, 0.f);
    float4 a1 = a0;
    if (inimg) {
        a0 = reinterpret_cast<const float4*>(g_acc)[(size_t)(0 * BB + b) * HW + p];
        a1 = reinterpret_cast<const float4*>(g_acc)[(size_t)(1 * BB + b) * HW + p];
    }
    float i0 = 1.0f / (a0.w + EPSF);
    float i1 = 1.0f / (a1.w + EPSF);
    float f01r = a0.x * i0, f01g = a0.y * i0, f01b = a0.z * i0;
    float f10r = a1.x * i1, f10g = a1.y * i1, f10b = a1.z * i1;

    // Stage 1: load RAW w into halo; +inf outside image (erosion pad).
    {
        const float* w0 = g_acc + ((size_t)(0 * BB + b) * HW << 2) + 3;
        const float* w1 = g_acc + ((size_t)(1 * BB + b) * HW << 2) + 3;
#pragma unroll 2
        for (int idx = tid; idx < INH * INW; idx += NT) {
            int iy = idx / INW;
            int ix = idx - iy * INW;
            int hy = oy - 2 * R + iy;
            int hx = ox - 2 * R + ix;
            float v0 = PINF, v1 = PINF;
            if ((unsigned)hy < (unsigned)HH && (unsigned)hx < (unsigned)WW) {
                size_t o = ((size_t)hy * WW + hx) << 2;
                v0 = w0[o];
                v1 = w1[o];
            }
            S.s_in[0][iy][ix] = v0;
            S.s_in[1][iy][ix] = v1;
        }
    }
    __syncthreads();

    // Stage 2: horizontal min, 2 outputs per iteration (shared taps)
    {
        constexpr int HMW2 = HMW / 2;
        for (int idx = tid; idx < INH * HMW2; idx += NT) {
            int iy = idx / HMW2;
            int hx = (idx - iy * HMW2) * 2;
            // taps hx .. hx+WIN+1
            float c0 = S.s_in[0][iy][hx + 1];
            float c1 = S.s_in[1][iy][hx + 1];
#pragma unroll
            for (int dd = 2; dd <= WIN; ++dd) {
                c0 = fminf(c0, S.s_in[0][iy][hx + dd]);
                c1 = fminf(c1, S.s_in[1][iy][hx + dd]);
            }
            S.s_hm[0][iy][hx]     = fminf(S.s_in[0][iy][hx], c0);
            S.s_hm[1][iy][hx]     = fminf(S.s_in[1][iy][hx], c1);
            S.s_hm[0][iy][hx + 1] = fminf(c0, S.s_in[0][iy][hx + WIN + 1]);
            S.s_hm[1][iy][hx + 1] = fminf(c1, S.s_in[1][iy][hx + WIN + 1]);
        }
    }
    __syncthreads();

    // Stage 3: vertical min -> erosion, 2 outputs per iteration (pair in ey);
    // out-of-image -> -inf (dilation pad)
    {
        constexpr int EH2 = EH / 2;
        for (int idx = tid; idx < EH2 * HMW; idx += NT) {
            int ep = idx / HMW;
            int hx = idx - ep * HMW;
            int ey = ep * 2;
            int hgx = ox - R + hx;
            bool colok = (unsigned)hgx < (unsigned)WW;
            int hy0 = oy - R + ey;
            float c0 = S.s_hm[0][ey + 1][hx];
            float c1 = S.s_hm[1][ey + 1][hx];
#pragma unroll
            for (int dd = 2; dd <= WIN; ++dd) {
                c0 = fminf(c0, S.s_hm[0][ey + dd][hx]);
                c1 = fminf(c1, S.s_hm[1][ey + dd][hx]);
            }
            bool ok0 = colok && ((unsigned)hy0 < (unsigned)HH);
            bool ok1 = colok && ((unsigned)(hy0 + 1) < (unsigned)HH);
            S.s_er[0][ey][hx]     = ok0 ? fminf(S.s_hm[0][ey][hx], c0) : NINF;
            S.s_er[1][ey][hx]     = ok0 ? fminf(S.s_hm[1][ey][hx], c1) : NINF;
            S.s_er[0][ey + 1][hx] = ok1 ? fminf(c0, S.s_hm[0][ey + WIN + 1][hx]) : NINF;
            S.s_er[1][ey + 1][hx] = ok1 ? fminf(c1, S.s_hm[1][ey + WIN + 1][hx]) : NINF;
        }
    }
    __syncthreads();

    // Stage 4: horizontal max, 2 outputs per iteration
    {
        constexpr int TTX2 = TTX / 2;
        for (int idx = tid; idx < EH * TTX2; idx += NT) {
            int ey = idx / TTX2;
            int xx = (idx - ey * TTX2) * 2;
            float c0 = S.s_er[0][ey][xx + 1];
            float c1 = S.s_er[1][ey][xx + 1];
#pragma unroll
            for (int dd = 2; dd <= WIN; ++dd) {
                c0 = fmaxf(c0, S.s_er[0][ey][xx + dd]);
                c1 = fmaxf(c1, S.s_er[1][ey][xx + dd]);
            }
            S.s_hx[0][ey][xx]     = fmaxf(S.s_er[0][ey][xx], c0);
            S.s_hx[1][ey][xx]     = fmaxf(S.s_er[1][ey][xx], c1);
            S.s_hx[0][ey][xx + 1] = fmaxf(c0, S.s_er[0][ey][xx + WIN + 1]);
            S.s_hx[1][ey][xx + 1] = fmaxf(c1, S.s_er[1][ey][xx + WIN + 1]);
        }
    }
    __syncthreads();

    // Stage 5: vertical max -> opened raw w; apply f(w)=w/(w+eps); compose.
    if (inimg) {
        float w01 = S.s_hx[0][tyy][txx];
        float w10 = S.s_hx[1][tyy][txx];
#pragma unroll
        for (int dd = 1; dd <= WIN; ++dd) {
            w01 = fmaxf(w01, S.s_hx[0][tyy + dd][txx]);
            w10 = fmaxf(w10, S.s_hx[1][tyy + dd][txx]);
        }
        float m01 = w01 / (w01 + EPSF);
        float m10 = w10 / (w10 + EPSF);

        float* ob = out + (size_t)b * 18 * HW;
        __stcs(&ob[(size_t)0  * HW + p], m01 * f01r + (1.0f - m01) * f10r);
        __stcs(&ob[(size_t)1  * HW + p], m01 * f01g + (1.0f - m01) * f10g);
        __stcs(&ob[(size_t)2  * HW + p], m01 * f01b + (1.0f - m01) * f10b);
        __stcs(&ob[(size_t)3  * HW + p], m10 * f10r + (1.0f - m10) * f01r);
        __stcs(&ob[(size_t)4  * HW + p], m10 * f10g + (1.0f - m10) * f01g);
        __stcs(&ob[(size_t)5  * HW + p], m10 * f10b + (1.0f - m10) * f01b);
        __stcs(&ob[(size_t)6  * HW + p], f01r);
        __stcs(&ob[(size_t)7  * HW + p], f01g);
        __stcs(&ob[(size_t)8  * HW + p], f01b);
        __stcs(&ob[(size_t)9  * HW + p], f10r);
        __stcs(&ob[(size_t)10 * HW + p], f10g);
        __stcs(&ob[(size_t)11 * HW + p], f10b);
        __stcs(&ob[(size_t)12 * HW + p], 0.5f * flow0[(size_t)(b * 2 + 0) * HW + p]);
        __stcs(&ob[(size_t)13 * HW + p], 0.5f * flow0[(size_t)(b * 2 + 1) * HW + p]);
        __stcs(&ob[(size_t)14 * HW + p], 0.5f * flow1[(size_t)(b * 2 + 0) * HW + p]);
        __stcs(&ob[(size_t)15 * HW + p], 0.5f * flow1[(size_t)(b * 2 + 1) * HW + p]);
        __stcs(&ob[(size_t)16 * HW + p], m01);
        __stcs(&ob[(size_t)17 * HW + p], m10);
    }
}

__global__ void __launch_bounds__(NT) open_compose_kernel(
    const int* __restrict__ kptr,
    const float* __restrict__ flow0, const float* __restrict__ flow1,
    float* __restrict__ out)
{
    __shared__ SmemT S;

    int kk = kptr[0];
    int r = (kk >= 2) ? (kk - 1) / 2 : 0;
    if (r > RMAX) r = RMAX;

    switch (r) {
        case 0: open_body<0>(S, flow0, flow1, out); break;
        case 1: open_body<1>(S, flow0, flow1, out); break;
        case 2: open_body<2>(S, flow0, flow1, out); break;
        case 3: open_body<3>(S, flow0, flow1, out); break;
        default: open_body<4>(S, flow0, flow1, out); break;
    }
}

// ---------------------------------------------------------------------------
extern "C" void kernel_launch(void* const* d_in, const int* in_sizes, int n_in,
                              void* d_out, int out_size)
{
    const float* img0  = (const float*)d_in[0];
    const float* img1  = (const float*)d_in[1];
    const float* flow0 = (const float*)d_in[2];
    const float* flow1 = (const float*)d_in[3];
    const float* z0    = (const float*)d_in[4];
    const float* z1    = (const float*)d_in[5];
    const int*   kptr  = (const int*)d_in[6];
    float* out = (float*)d_out;

    // Clear accumulators (memset node in the captured graph)
    void* accPtr = nullptr;
    cudaGetSymbolAddress(&accPtr, g_acc);
    cudaMemsetAsync(accPtr, 0, sizeof(float) * (size_t)2 * BB * HW * 4, 0);

    int threads = 256;
    int blocks = (NPIX + threads - 1) / threads;
    splat_kernel<<<blocks, threads>>>(img0, img1, flow0, flow1, z0, z1);

    dim3 gblk(TTX, TTY, 1);
    dim3 ggrid((WW + TTX - 1) / TTX, (HH + TTY - 1) / TTY, BB);
    open_compose_kernel<<<ggrid, gblk>>>(kptr, flow0, flow1, out);
}

// round 8
// speedup vs baseline: 1.2527x; 1.0242x over previous
#include <cuda_runtime.h>
#include <math.h>

#define BB 2
#define HH 720
#define WW 1280
#define HW (HH*WW)
#define NPIX (BB*HW)
#define EPSF 1e-7f

// Scratch: splat accumulators [dir][b][pixel][4ch]  (~59 MB)
__device__ __align__(16) float g_acc[(size_t)2 * BB * HW * 4];

// ---------------------------------------------------------------------------
// Splat kernel, ONE direction per launch (scalar, 1 px/thread — REDG floor).
// sm_90+ float4 atomicAdd -> one RED.E.128 per corner.
// ---------------------------------------------------------------------------
__global__ void __launch_bounds__(256) splat_dir_kernel(
    const float* __restrict__ img, const float* __restrict__ fl,
    const float* __restrict__ zz, float4* __restrict__ accBase)
{
    int i = blockIdx.x * blockDim.x + threadIdx.x;
    if (i >= NPIX) return;
    int b = i / HW;
    int p = i - b * HW;
    int y = p / WW;
    int x = p - y * WW;

    float fx = (float)x + 0.5f * fl[(size_t)(b * 2 + 1) * HW + p];
    float fy = (float)y + 0.5f * fl[(size_t)(b * 2 + 0) * HW + p];
    float w  = __expf(zz[(size_t)b * HW + p]);
    float vr = img[(size_t)(b * 3 + 0) * HW + p] * w;
    float vg = img[(size_t)(b * 3 + 1) * HW + p] * w;
    float vb = img[(size_t)(b * 3 + 2) * HW + p] * w;

    float x0f = floorf(fx), y0f = floorf(fy);
    int ix0 = (int)x0f, iy0 = (int)y0f;
    float ax = fx - x0f, ay = fy - y0f;

    float4* acc = accBase + (size_t)b * HW;
#pragma unroll
    for (int cy = 0; cy < 2; ++cy) {
        int ty = iy0 + cy;
        if ((unsigned)ty >= (unsigned)HH) continue;
        float wy = cy ? ay : (1.0f - ay);
#pragma unroll
        for (int cx = 0; cx < 2; ++cx) {
            int tx = ix0 + cx;
            if ((unsigned)tx >= (unsigned)WW) continue;
            float wt = wy * (cx ? ax : (1.0f - ax));
            atomicAdd(acc + ((size_t)ty * WW + tx),
                      make_float4(vr * wt, vg * wt, vb * wt, w * wt));
        }
    }
}

// ---------------------------------------------------------------------------
// Fused normalize + morphological open + compose.
// - open() on RAW w (monotone map at the end)
// - both masks interleaved; sliding-window pairs in stages 2-4
// - streaming stores; occupancy forced to 4 blocks/SM (regs<=32)
// Tile 32x16, 512 threads, template-specialized on radius R.
// Grid divides H,W exactly -> no center bounds checks.
// ---------------------------------------------------------------------------
#define TTX 32
#define TTY 16
#define RMAX 4
#define INW_MAX (TTX + 4 * RMAX)   // 48
#define INH_MAX (TTY + 4 * RMAX)   // 32
#define HMW_MAX (TTX + 2 * RMAX)   // 40
#define EH_MAX  (TTY + 2 * RMAX)   // 24
#define NT (TTX * TTY)

struct SmemT {
    float s_in[2][INH_MAX][INW_MAX];
    float s_hm[2][INH_MAX][HMW_MAX];
    float s_er[2][EH_MAX][HMW_MAX];
    float s_hx[2][EH_MAX][TTX];
};

template<int R>
__device__ __forceinline__ void open_body(
    SmemT& S,
    const float* __restrict__ flow0, const float* __restrict__ flow1,
    float* __restrict__ out)
{
    constexpr int INW = TTX + 4 * R;
    constexpr int INH = TTY + 4 * R;
    constexpr int HMW = TTX + 2 * R;   // even
    constexpr int EH  = TTY + 2 * R;   // even
    constexpr int WIN = 2 * R;

    const float PINF = __int_as_float(0x7f800000);
    const float NINF = __int_as_float(0xff800000);

    int b  = blockIdx.z;
    int ox = blockIdx.x * TTX;
    int oy = blockIdx.y * TTY;
    int tid = threadIdx.y * TTX + threadIdx.x;

    int txx = threadIdx.x, tyy = threadIdx.y;
    int gx = ox + txx, gy = oy + tyy;
    size_t p = (size_t)gy * WW + gx;
    float4 a0 = reinterpret_cast<const float4*>(g_acc)[(size_t)(0 * BB + b) * HW + p];
    float4 a1 = reinterpret_cast<const float4*>(g_acc)[(size_t)(1 * BB + b) * HW + p];
    float i0 = 1.0f / (a0.w + EPSF);
    float i1 = 1.0f / (a1.w + EPSF);
    float f01r = a0.x * i0, f01g = a0.y * i0, f01b = a0.z * i0;
    float f10r = a1.x * i1, f10g = a1.y * i1, f10b = a1.z * i1;

    // Stage 1: load RAW w into halo; +inf outside image (erosion pad).
    {
        const float* w0 = g_acc + ((size_t)(0 * BB + b) * HW << 2) + 3;
        const float* w1 = g_acc + ((size_t)(1 * BB + b) * HW << 2) + 3;
#pragma unroll 2
        for (int idx = tid; idx < INH * INW; idx += NT) {
            int iy = idx / INW;
            int ix = idx - iy * INW;
            int hy = oy - 2 * R + iy;
            int hx = ox - 2 * R + ix;
            float v0 = PINF, v1 = PINF;
            if ((unsigned)hy < (unsigned)HH && (unsigned)hx < (unsigned)WW) {
                size_t o = ((size_t)hy * WW + hx) << 2;
                v0 = w0[o];
                v1 = w1[o];
            }
            S.s_in[0][iy][ix] = v0;
            S.s_in[1][iy][ix] = v1;
        }
    }
    __syncthreads();

    // Stage 2: horizontal min, 2 outputs per iteration (shared taps)
    {
        constexpr int HMW2 = HMW / 2;
        for (int idx = tid; idx < INH * HMW2; idx += NT) {
            int iy = idx / HMW2;
            int hx = (idx - iy * HMW2) * 2;
            float c0 = S.s_in[0][iy][hx + 1];
            float c1 = S.s_in[1][iy][hx + 1];
#pragma unroll
            for (int dd = 2; dd <= WIN; ++dd) {
                c0 = fminf(c0, S.s_in[0][iy][hx + dd]);
                c1 = fminf(c1, S.s_in[1][iy][hx + dd]);
            }
            S.s_hm[0][iy][hx]     = fminf(S.s_in[0][iy][hx], c0);
            S.s_hm[1][iy][hx]     = fminf(S.s_in[1][iy][hx], c1);
            S.s_hm[0][iy][hx + 1] = fminf(c0, S.s_in[0][iy][hx + WIN + 1]);
            S.s_hm[1][iy][hx + 1] = fminf(c1, S.s_in[1][iy][hx + WIN + 1]);
        }
    }
    __syncthreads();

    // Stage 3: vertical min -> erosion, 2 outputs per iteration;
    // out-of-image -> -inf (dilation pad)
    {
        constexpr int EH2 = EH / 2;
        for (int idx = tid; idx < EH2 * HMW; idx += NT) {
            int ep = idx / HMW;
            int hx = idx - ep * HMW;
            int ey = ep * 2;
            int hgx = ox - R + hx;
            bool colok = (unsigned)hgx < (unsigned)WW;
            int hy0 = oy - R + ey;
            float c0 = S.s_hm[0][ey + 1][hx];
            float c1 = S.s_hm[1][ey + 1][hx];
#pragma unroll
            for (int dd = 2; dd <= WIN; ++dd) {
                c0 = fminf(c0, S.s_hm[0][ey + dd][hx]);
                c1 = fminf(c1, S.s_hm[1][ey + dd][hx]);
            }
            bool ok0 = colok && ((unsigned)hy0 < (unsigned)HH);
            bool ok1 = colok && ((unsigned)(hy0 + 1) < (unsigned)HH);
            S.s_er[0][ey][hx]     = ok0 ? fminf(S.s_hm[0][ey][hx], c0) : NINF;
            S.s_er[1][ey][hx]     = ok0 ? fminf(S.s_hm[1][ey][hx], c1) : NINF;
            S.s_er[0][ey + 1][hx] = ok1 ? fminf(c0, S.s_hm[0][ey + WIN + 1][hx]) : NINF;
            S.s_er[1][ey + 1][hx] = ok1 ? fminf(c1, S.s_hm[1][ey + WIN + 1][hx]) : NINF;
        }
    }
    __syncthreads();

    // Stage 4: horizontal max, 2 outputs per iteration
    {
        constexpr int TTX2 = TTX / 2;
        for (int idx = tid; idx < EH * TTX2; idx += NT) {
            int ey = idx / TTX2;
            int xx = (idx - ey * TTX2) * 2;
            float c0 = S.s_er[0][ey][xx + 1];
            float c1 = S.s_er[1][ey][xx + 1];
#pragma unroll
            for (int dd = 2; dd <= WIN; ++dd) {
                c0 = fmaxf(c0, S.s_er[0][ey][xx + dd]);
                c1 = fmaxf(c1, S.s_er[1][ey][xx + dd]);
            }
            S.s_hx[0][ey][xx]     = fmaxf(S.s_er[0][ey][xx], c0);
            S.s_hx[1][ey][xx]     = fmaxf(S.s_er[1][ey][xx], c1);
            S.s_hx[0][ey][xx + 1] = fmaxf(c0, S.s_er[0][ey][xx + WIN + 1]);
            S.s_hx[1][ey][xx + 1] = fmaxf(c1, S.s_er[1][ey][xx + WIN + 1]);
        }
    }
    __syncthreads();

    // Stage 5: vertical max -> opened raw w; apply f(w)=w/(w+eps); compose.
    {
        float w01 = S.s_hx[0][tyy][txx];
        float w10 = S.s_hx[1][tyy][txx];
#pragma unroll
        for (int dd = 1; dd <= WIN; ++dd) {
            w01 = fmaxf(w01, S.s_hx[0][tyy + dd][txx]);
            w10 = fmaxf(w10, S.s_hx[1][tyy + dd][txx]);
        }
        float m01 = w01 / (w01 + EPSF);
        float m10 = w10 / (w10 + EPSF);

        float* ob = out + (size_t)b * 18 * HW;
        __stcs(&ob[(size_t)0  * HW + p], m01 * f01r + (1.0f - m01) * f10r);
        __stcs(&ob[(size_t)1  * HW + p], m01 * f01g + (1.0f - m01) * f10g);
        __stcs(&ob[(size_t)2  * HW + p], m01 * f01b + (1.0f - m01) * f10b);
        __stcs(&ob[(size_t)3  * HW + p], m10 * f10r + (1.0f - m10) * f01r);
        __stcs(&ob[(size_t)4  * HW + p], m10 * f10g + (1.0f - m10) * f01g);
        __stcs(&ob[(size_t)5  * HW + p], m10 * f10b + (1.0f - m10) * f01b);
        __stcs(&ob[(size_t)6  * HW + p], f01r);
        __stcs(&ob[(size_t)7  * HW + p], f01g);
        __stcs(&ob[(size_t)8  * HW + p], f01b);
        __stcs(&ob[(size_t)9  * HW + p], f10r);
        __stcs(&ob[(size_t)10 * HW + p], f10g);
        __stcs(&ob[(size_t)11 * HW + p], f10b);
        __stcs(&ob[(size_t)12 * HW + p], 0.5f * flow0[(size_t)(b * 2 + 0) * HW + p]);
        __stcs(&ob[(size_t)13 * HW + p], 0.5f * flow0[(size_t)(b * 2 + 1) * HW + p]);
        __stcs(&ob[(size_t)14 * HW + p], 0.5f * flow1[(size_t)(b * 2 + 0) * HW + p]);
        __stcs(&ob[(size_t)15 * HW + p], 0.5f * flow1[(size_t)(b * 2 + 1) * HW + p]);
        __stcs(&ob[(size_t)16 * HW + p], m01);
        __stcs(&ob[(size_t)17 * HW + p], m10);
    }
}

__global__ void __launch_bounds__(NT, 4) open_compose_kernel(
    const int* __restrict__ kptr,
    const float* __restrict__ flow0, const float* __restrict__ flow1,
    float* __restrict__ out)
{
    __shared__ SmemT S;

    int kk = kptr[0];
    int r = (kk >= 2) ? (kk - 1) / 2 : 0;
    if (r > RMAX) r = RMAX;

    switch (r) {
        case 0: open_body<0>(S, flow0, flow1, out); break;
        case 1: open_body<1>(S, flow0, flow1, out); break;
        case 2: open_body<2>(S, flow0, flow1, out); break;
        case 3: open_body<3>(S, flow0, flow1, out); break;
        default: open_body<4>(S, flow0, flow1, out); break;
    }
}

// ---------------------------------------------------------------------------
extern "C" void kernel_launch(void* const* d_in, const int* in_sizes, int n_in,
                              void* d_out, int out_size)
{
    const float* img0  = (const float*)d_in[0];
    const float* img1  = (const float*)d_in[1];
    const float* flow0 = (const float*)d_in[2];
    const float* flow1 = (const float*)d_in[3];
    const float* z0    = (const float*)d_in[4];
    const float* z1    = (const float*)d_in[5];
    const int*   kptr  = (const int*)d_in[6];
    float* out = (float*)d_out;

    // One-time host-side resources (no device memory involved)
    static cudaStream_t s1 = nullptr;
    static cudaEvent_t evFork = nullptr, evJoin = nullptr;
    if (s1 == nullptr) {
        cudaStreamCreateWithFlags(&s1, cudaStreamNonBlocking);
        cudaEventCreateWithFlags(&evFork, cudaEventDisableTiming);
        cudaEventCreateWithFlags(&evJoin, cudaEventDisableTiming);
    }

    void* accPtr = nullptr;
    cudaGetSymbolAddress(&accPtr, g_acc);
    const size_t dirBytes = sizeof(float) * (size_t)BB * HW * 4;
    float4* acc_d0 = reinterpret_cast<float4*>(accPtr);
    float4* acc_d1 = acc_d0 + (size_t)BB * HW;

    int threads = 256;
    int blocks = (NPIX + threads - 1) / threads;

    // Fork: direction 1 (memset + splat) on side stream, overlapping
    // direction 0's memset/splat on the main stream.
    cudaEventRecord(evFork, 0);
    cudaStreamWaitEvent(s1, evFork, 0);

    // Main stream: dir 0 = img0 splat with flow1/z1
    cudaMemsetAsync(acc_d0, 0, dirBytes, 0);
    splat_dir_kernel<<<blocks, threads, 0, 0>>>(img0, flow1, z1, acc_d0);

    // Side stream: dir 1 = img1 splat with flow0/z0
    cudaMemsetAsync(acc_d1, 0, dirBytes, s1);
    splat_dir_kernel<<<blocks, threads, 0, s1>>>(img1, flow0, z0, acc_d1);

    // Join
    cudaEventRecord(evJoin, s1);
    cudaStreamWaitEvent(0, evJoin, 0);

    dim3 gblk(TTX, TTY, 1);
    dim3 ggrid(WW / TTX, HH / TTY, BB);
    open_compose_kernel<<<ggrid, gblk, 0, 0>>>(kptr, flow0, flow1, out);
}